// round 8
// baseline (speedup 1.0000x reference)
#include <cuda_runtime.h>
#include <cstdint>
#include <float.h>

#define NG 5
#define NB 131072
#define NK 512
#define ND 64
#define MTILE 256
#define CTA 512
#define XBLK (NB / MTILE)        // 512
#define NCTAS (NG * XBLK)        // 2560
#define CAP 8
#define EPS 0.002f
#define PAD 68                   // float stride per row (4-bank shift, conflict-free)

__device__ double g_loss_sum[NG];
__device__ unsigned int g_done = 0;

__device__ __forceinline__ uint32_t cvt_tf32(float f) {
    uint32_t r;
    asm("cvt.rna.tf32.f32 %0, %1;" : "=r"(r) : "f"(f));
    return r;
}
__device__ __forceinline__ void mma_tf32(float acc[4], const uint32_t a[4],
                                         uint32_t b0, uint32_t b1) {
    asm("mma.sync.aligned.m16n8k8.row.col.f32.tf32.tf32.f32 "
        "{%0,%1,%2,%3},{%4,%5,%6,%7},{%8,%9},{%0,%1,%2,%3};"
        : "+f"(acc[0]), "+f"(acc[1]), "+f"(acc[2]), "+f"(acc[3])
        : "r"(a[0]), "r"(a[1]), "r"(a[2]), "r"(a[3]), "r"(b0), "r"(b1));
}

__global__ __launch_bounds__(CTA, 1) void vq_mma_kernel(
    const float* __restrict__ feat,   // [G,B,D]
    const float* __restrict__ cb,     // [G,K,D]
    float* __restrict__ out_q,        // [G,B,D]
    float* __restrict__ out_loss,     // [G+1]
    float* __restrict__ out_idx,      // [G,B] as float
    int write_q, int write_loss, int write_idx)
{
    extern __shared__ float sh[];
    uint32_t* sh_cbt  = (uint32_t*)sh;                    // [512][PAD] tf32
    float*    sh_feat = sh + (size_t)NK * PAD;            // [256][PAD] fp32
    float*    sh_esq  = sh_feat + (size_t)MTILE * PAD;    // [512]
    float*    sh_xsq  = sh_esq + NK;                       // [256]
    int*      sh_bk   = (int*)(sh_xsq + MTILE);            // [256]
    float*    sh_red  = (float*)(sh_bk + MTILE);           // [16]

    const int tid = threadIdx.x;
    const int lane = tid & 31;
    const int wid = tid >> 5;                 // 0..15
    const int g = blockIdx.y;
    const int base_row = blockIdx.x * MTILE;
    const float* cbg = cb + (size_t)g * NK * ND;

    // ---- Stage features fp32 (padded) ----
    {
        const float4* xin = (const float4*)(feat + ((size_t)g * NB + base_row) * ND);
        #pragma unroll
        for (int it = 0; it < (MTILE * ND / 4) / CTA; it++) {
            int i = it * CTA + tid;
            float4 v = xin[i];
            int row = i >> 4, c4 = i & 15;
            *(float4*)(sh_feat + (size_t)row * PAD + 4 * c4) = v;
        }
    }
    // ---- Stage codebook tf32 (padded) ----
    {
        const float4* cin = (const float4*)cbg;
        #pragma unroll
        for (int it = 0; it < (NK * ND / 4) / CTA; it++) {
            int i = it * CTA + tid;
            float4 v = cin[i];
            int n = i >> 4, c4 = i & 15;
            uint32_t* p = sh_cbt + (size_t)n * PAD + 4 * c4;
            p[0] = cvt_tf32(v.x);
            p[1] = cvt_tf32(v.y);
            p[2] = cvt_tf32(v.z);
            p[3] = cvt_tf32(v.w);
        }
    }
    // ---- Exact e_sq (sequential-d chain, one codeword per thread) ----
    {
        const float4* cp = (const float4*)(cbg + (size_t)tid * ND);
        float acc = 0.f;
        #pragma unroll
        for (int i = 0; i < 16; i++) {
            float4 v = cp[i];
            acc = fmaf(v.x, v.x, acc);
            acc = fmaf(v.y, v.y, acc);
            acc = fmaf(v.z, v.z, acc);
            acc = fmaf(v.w, v.w, acc);
        }
        sh_esq[tid] = acc;
    }
    __syncthreads();

    // ---- Exact x_sq per row (sequential-d chain) ----
    if (tid < MTILE) {
        const float4* xp = (const float4*)(sh_feat + (size_t)tid * PAD);
        float acc = 0.f;
        #pragma unroll
        for (int i = 0; i < 16; i++) {
            float4 v = xp[i];
            acc = fmaf(v.x, v.x, acc);
            acc = fmaf(v.y, v.y, acc);
            acc = fmaf(v.z, v.z, acc);
            acc = fmaf(v.w, v.w, acc);
        }
        sh_xsq[tid] = acc;
    }
    __syncthreads();

    // ---- A fragments: rows rA=wrb+lane/4, rB=rA+8, all 8 k-steps (tf32) ----
    const int wrb = wid * 16;
    const int qc = lane & 3;                 // quad column
    const int rA = wrb + (lane >> 2);
    const int rB = rA + 8;
    uint32_t afr[8][4];
    #pragma unroll
    for (int ks = 0; ks < 8; ks++) {
        afr[ks][0] = cvt_tf32(sh_feat[(size_t)rA * PAD + 8 * ks + qc]);
        afr[ks][1] = cvt_tf32(sh_feat[(size_t)rB * PAD + 8 * ks + qc]);
        afr[ks][2] = cvt_tf32(sh_feat[(size_t)rA * PAD + 8 * ks + qc + 4]);
        afr[ks][3] = cvt_tf32(sh_feat[(size_t)rB * PAD + 8 * ks + qc + 4]);
    }
    const float xsqA = sh_xsq[rA];
    const float xsqB = sh_xsq[rB];

    // ---- Approx scan over 64 n-tiles: provisional min + candidates ----
    float provA = FLT_MAX, provB = FLT_MAX;
    int cntA = 0, cntB = 0;
    int candA[CAP], candB[CAP];
    #pragma unroll 1
    for (int nt = 0; nt < 64; nt++) {
        float acc[4] = {0.f, 0.f, 0.f, 0.f};
        const uint32_t* bp = sh_cbt + (size_t)(nt * 8 + (lane >> 2)) * PAD + qc;
        #pragma unroll
        for (int ks = 0; ks < 8; ks++)
            mma_tf32(acc, afr[ks], bp[8 * ks], bp[8 * ks + 4]);

        const int n0 = nt * 8 + 2 * qc;
        const float e0 = sh_esq[n0], e1 = sh_esq[n0 + 1];
        float dA0 = (xsqA + e0) - 2.0f * acc[0];
        float dA1 = (xsqA + e1) - 2.0f * acc[1];
        float dB0 = (xsqB + e0) - 2.0f * acc[2];
        float dB1 = (xsqB + e1) - 2.0f * acc[3];
        provA = fminf(provA, fminf(dA0, dA1));
        provB = fminf(provB, fminf(dB0, dB1));
        float thA = provA + EPS, thB = provB + EPS;
        if (dA0 <= thA) { if (cntA < CAP) candA[cntA] = n0;     cntA++; }
        if (dA1 <= thA) { if (cntA < CAP) candA[cntA] = n0 + 1; cntA++; }
        if (dB0 <= thB) { if (cntB < CAP) candB[cntB] = n0;     cntB++; }
        if (dB1 <= thB) { if (cntB < CAP) candB[cntB] = n0 + 1; cntB++; }
    }

    // ---- Exact phase: fp32 sequential-d chains on candidates ----
    #define EXACT_K(kk, xrow, xsq_, best, bk)                                  \
    {                                                                          \
        const float4* cp = (const float4*)(cbg + (size_t)(kk) * ND);           \
        const float4* xp = (const float4*)(xrow);                              \
        float cr = 0.f;                                                        \
        _Pragma("unroll")                                                      \
        for (int i = 0; i < 16; i++) {                                         \
            float4 v = cp[i];                                                  \
            float4 x = xp[i];                                                  \
            cr = fmaf(x.x, v.x, cr);                                           \
            cr = fmaf(x.y, v.y, cr);                                           \
            cr = fmaf(x.z, v.z, cr);                                           \
            cr = fmaf(x.w, v.w, cr);                                           \
        }                                                                      \
        float dk = (xsq_ + sh_esq[kk]) - 2.0f * cr;                            \
        if (dk < best || (dk == best && (kk) < bk)) { best = dk; bk = (kk); }  \
    }
    float bestA = FLT_MAX, bestB = FLT_MAX;
    int bkA = 0, bkB = 0;
    const float* xrowA = sh_feat + (size_t)rA * PAD;
    const float* xrowB = sh_feat + (size_t)rB * PAD;
    if (cntA > CAP) {
        for (int k = 0; k < NK; k++) EXACT_K(k, xrowA, xsqA, bestA, bkA);
    } else {
        for (int i = 0; i < cntA; i++) { int k = candA[i]; EXACT_K(k, xrowA, xsqA, bestA, bkA); }
    }
    if (cntB > CAP) {
        for (int k = 0; k < NK; k++) EXACT_K(k, xrowB, xsqB, bestB, bkB);
    } else {
        for (int i = 0; i < cntB; i++) { int k = candB[i]; EXACT_K(k, xrowB, xsqB, bestB, bkB); }
    }
    #undef EXACT_K

    // ---- Quad reduction (4 lanes cover all 512 cols per row), tie -> smaller k ----
    #pragma unroll
    for (int m = 1; m < 4; m <<= 1) {
        float ob = __shfl_xor_sync(0xFFFFFFFFu, bestA, m);
        int   ok = __shfl_xor_sync(0xFFFFFFFFu, bkA, m);
        if (ob < bestA || (ob == bestA && ok < bkA)) { bestA = ob; bkA = ok; }
        ob = __shfl_xor_sync(0xFFFFFFFFu, bestB, m);
        ok = __shfl_xor_sync(0xFFFFFFFFu, bkB, m);
        if (ob < bestB || (ob == bestB && ok < bkB)) { bestB = ob; bkB = ok; }
    }
    if (qc == 0) {
        sh_bk[rA] = bkA;
        sh_bk[rB] = bkB;
    }
    __syncthreads();

    // ---- Outputs: quantized_st = f + (q - f), indices, loss ----
    float lsum = 0.f;
    {
        float4* oq = (float4*)(out_q + ((size_t)g * NB + base_row) * ND);
        #pragma unroll
        for (int it = 0; it < (MTILE * ND / 4) / CTA; it++) {
            int i = it * CTA + tid;
            int row = i >> 4, c4 = i & 15;
            int k = sh_bk[row];
            float4 qv = *((const float4*)(cbg + (size_t)k * ND) + c4);
            float4 fv = *(const float4*)(sh_feat + (size_t)row * PAD + 4 * c4);
            float dx0 = qv.x - fv.x, dx1 = qv.y - fv.y;
            float dx2 = qv.z - fv.z, dx3 = qv.w - fv.w;
            lsum = fmaf(dx0, dx0, lsum);
            lsum = fmaf(dx1, dx1, lsum);
            lsum = fmaf(dx2, dx2, lsum);
            lsum = fmaf(dx3, dx3, lsum);
            if (write_q)
                oq[i] = make_float4(fv.x + dx0, fv.y + dx1, fv.z + dx2, fv.w + dx3);
        }
    }
    if (write_idx && tid < MTILE)
        out_idx[(size_t)g * NB + base_row + tid] = (float)sh_bk[tid];

    // ---- Loss: warp shuffle -> shared -> double atomic; last CTA finalizes ----
    #pragma unroll
    for (int off = 16; off > 0; off >>= 1)
        lsum += __shfl_xor_sync(0xFFFFFFFFu, lsum, off);
    if (lane == 0) sh_red[wid] = lsum;
    __syncthreads();
    if (tid == 0) {
        double s = 0.0;
        #pragma unroll
        for (int w = 0; w < CTA / 32; w++) s += (double)sh_red[w];
        atomicAdd(&g_loss_sum[g], s);
        __threadfence();
        unsigned int t = atomicAdd(&g_done, 1u);
        if (t == NCTAS - 1) {
            __threadfence();
            if (write_loss) {
                const double inv = 1.25 / ((double)NB * (double)ND);
                float tot = 0.f;
                for (int g2 = 0; g2 < NG; g2++) {
                    float pl = (float)(g_loss_sum[g2] * inv);
                    out_loss[g2] = pl;
                    tot += pl;
                }
                out_loss[NG] = tot;
            }
            for (int g2 = 0; g2 < NG; g2++) g_loss_sum[g2] = 0.0;
            g_done = 0;
        }
    }
}

extern "C" void kernel_launch(void* const* d_in, const int* in_sizes, int n_in,
                              void* d_out, int out_size) {
    const float* feat = (const float*)d_in[0];
    const float* cb   = (const float*)d_in[1];
    if (n_in >= 2 && in_sizes[0] == NG * NK * ND) {
        const float* t = feat; feat = cb; cb = t;
    }
    float* out = (float*)d_out;

    const long long q_elems   = (long long)NG * NB * ND;
    const long long idx_elems = (long long)NG * NB;
    const long long full_sz   = q_elems + NG + 1 + idx_elems;
    const int write_q    = ((long long)out_size >= q_elems);
    const int write_loss = ((long long)out_size >= q_elems + NG + 1);
    const int write_idx  = ((long long)out_size >= full_sz);

    // smem: cb tf32 512*68*4 + feat 256*68*4 + esq 2048 + xsq 1024 + bk 1024 + red 64
    const int smem_bytes = (NK * PAD + MTILE * PAD) * 4 + NK * 4 + MTILE * 4 + MTILE * 4 + 64;
    cudaFuncSetAttribute(vq_mma_kernel,
                         cudaFuncAttributeMaxDynamicSharedMemorySize, smem_bytes);

    dim3 grid(XBLK, NG);
    float* out_loss = out + q_elems;
    float* out_idx  = out + q_elems + NG + 1;
    vq_mma_kernel<<<grid, CTA, smem_bytes>>>(feat, cb, out, out_loss, out_idx,
                                             write_q, write_loss, write_idx);
}

// round 9
// speedup vs baseline: 11.6676x; 11.6676x over previous
#include <cuda_runtime.h>
#include <cstdint>
#include <float.h>

#define NG 5
#define NB 131072
#define NK 512
#define ND 64
#define CTA 256
#define ROWS_PER_CTA 512
#define XBLK (NB / ROWS_PER_CTA)   // 256
#define NCTAS (NG * XBLK)          // 1280
#define CAP 20
#define DC 7.6895e-6f              // 0.5 / 65024 (codebook quantization step bound)

__device__ double g_loss_sum[NG];
__device__ unsigned int g_done = 0;

__global__ __launch_bounds__(CTA, 2) void vq_dp4a_kernel(
    const float* __restrict__ feat,   // [G,B,D]
    const float* __restrict__ cb,     // [G,K,D]
    float* __restrict__ out_q,        // [G,B,D]
    float* __restrict__ out_loss,     // [G+1]
    float* __restrict__ out_idx,      // [G,B] as float
    int write_q, int write_loss, int write_idx)
{
    __shared__ uint32_t sh_cpk[NK * 16];   // int8-packed codebook [k][d/4]
    __shared__ float sh_esq[NK];
    __shared__ int sh_smax;                // max_k sum|c| as ordered int
    __shared__ float sh_red[8];

    const int tid = threadIdx.x;
    const int g = blockIdx.y;
    const int base_row = blockIdx.x * ROWS_PER_CTA;
    const float* cbg = cb + (size_t)g * NK * ND;
    const size_t gNB = (size_t)g * NB;

    if (tid == 0) sh_smax = 0;
    __syncthreads();

    // ---- Pack codebook to int8, exact e_sq (validated sequential-d chain), sum|c| ----
    #pragma unroll
    for (int s2 = 0; s2 < 2; s2++) {
        const int k = tid + s2 * CTA;
        const float4* cp = (const float4*)(cbg + (size_t)k * ND);
        float esqa = 0.f, sab = 0.f;
        #pragma unroll
        for (int i = 0; i < 16; i++) {
            float4 v = cp[i];
            esqa = fmaf(v.x, v.x, esqa);
            esqa = fmaf(v.y, v.y, esqa);
            esqa = fmaf(v.z, v.z, esqa);
            esqa = fmaf(v.w, v.w, esqa);
            sab += fabsf(v.x) + fabsf(v.y) + fabsf(v.z) + fabsf(v.w);
            int q0 = __float2int_rn(v.x * 65024.f);
            int q1 = __float2int_rn(v.y * 65024.f);
            int q2 = __float2int_rn(v.z * 65024.f);
            int q3 = __float2int_rn(v.w * 65024.f);
            sh_cpk[k * 16 + i] = (uint32_t)(q0 & 0xFF) | ((uint32_t)(q1 & 0xFF) << 8) |
                                 ((uint32_t)(q2 & 0xFF) << 16) | ((uint32_t)q3 << 24);
        }
        sh_esq[k] = esqa;
        atomicMax(&sh_smax, __float_as_int(sab));
    }
    __syncthreads();
    const float smaxf = __int_as_float(sh_smax);

    // ---- Pack this thread's 2 feature rows to int8; exact x_sq; rigorous EPS ----
    const int row0 = base_row + tid;
    uint32_t qx0[16], qx1[16];
    float xsq0, xsq1, fn0, fn1, eps0, eps1;
    #pragma unroll
    for (int r = 0; r < 2; r++) {
        const float4* xin = (const float4*)(feat + (gNB + row0 + r * CTA) * ND);
        float4 xv[16];
        float xsq = 0.f, mx = 1e-20f, sx = 0.f;
        #pragma unroll
        for (int i = 0; i < 16; i++) {
            float4 v = xin[i];
            xv[i] = v;
            xsq = fmaf(v.x, v.x, xsq);
            xsq = fmaf(v.y, v.y, xsq);
            xsq = fmaf(v.z, v.z, xsq);
            xsq = fmaf(v.w, v.w, xsq);
            mx = fmaxf(mx, fabsf(v.x)); mx = fmaxf(mx, fabsf(v.y));
            mx = fmaxf(mx, fabsf(v.z)); mx = fmaxf(mx, fabsf(v.w));
            sx += fabsf(v.x) + fabsf(v.y) + fabsf(v.z) + fabsf(v.w);
        }
        const float s = 126.f / mx;
        uint32_t* qx = r ? qx1 : qx0;
        #pragma unroll
        for (int i = 0; i < 16; i++) {
            int q0 = __float2int_rn(xv[i].x * s);
            int q1 = __float2int_rn(xv[i].y * s);
            int q2 = __float2int_rn(xv[i].z * s);
            int q3 = __float2int_rn(xv[i].w * s);
            qx[i] = (uint32_t)(q0 & 0xFF) | ((uint32_t)(q1 & 0xFF) << 8) |
                    ((uint32_t)(q2 & 0xFF) << 16) | ((uint32_t)q3 << 24);
        }
        const float dx = 0.5f / s;
        const float B = 2.f * (sx * DC + smaxf * dx + 64.f * dx * DC);
        const float eps = B * 1.25f + 1e-6f;
        const float fn = -2.f / (s * 65024.f);
        if (r == 0) { xsq0 = xsq; fn0 = fn; eps0 = eps; }
        else        { xsq1 = xsq; fn1 = fn; eps1 = eps; }
    }

    // ---- DP4A approx scan: provisional min + candidate collection (2 k / iter) ----
    float pmin0 = FLT_MAX, pmin1 = FLT_MAX;
    int cnt0 = 0, cnt1 = 0;
    int cnd0[CAP], cnd1[CAP];
    float cdv0[CAP], cdv1[CAP];
    const uint4* cp4 = (const uint4*)sh_cpk;
    #pragma unroll 1
    for (int k = 0; k < NK; k += 2) {
        uint32_t wA[16], wB[16];
        {
            uint4 t;
            t = cp4[4 * k + 0]; wA[0] = t.x; wA[1] = t.y; wA[2]  = t.z; wA[3]  = t.w;
            t = cp4[4 * k + 1]; wA[4] = t.x; wA[5] = t.y; wA[6]  = t.z; wA[7]  = t.w;
            t = cp4[4 * k + 2]; wA[8] = t.x; wA[9] = t.y; wA[10] = t.z; wA[11] = t.w;
            t = cp4[4 * k + 3]; wA[12] = t.x; wA[13] = t.y; wA[14] = t.z; wA[15] = t.w;
            t = cp4[4 * k + 4]; wB[0] = t.x; wB[1] = t.y; wB[2]  = t.z; wB[3]  = t.w;
            t = cp4[4 * k + 5]; wB[4] = t.x; wB[5] = t.y; wB[6]  = t.z; wB[7]  = t.w;
            t = cp4[4 * k + 6]; wB[8] = t.x; wB[9] = t.y; wB[10] = t.z; wB[11] = t.w;
            t = cp4[4 * k + 7]; wB[12] = t.x; wB[13] = t.y; wB[14] = t.z; wB[15] = t.w;
        }
        int a00 = 0, a01 = 0, a10 = 0, a11 = 0;
        #pragma unroll
        for (int j = 0; j < 16; j++) {
            a00 = __dp4a((int)wA[j], (int)qx0[j], a00);
            a01 = __dp4a((int)wB[j], (int)qx0[j], a01);
            a10 = __dp4a((int)wA[j], (int)qx1[j], a10);
            a11 = __dp4a((int)wB[j], (int)qx1[j], a11);
        }
        const float e0 = sh_esq[k], e1 = sh_esq[k + 1];
        float d00 = fmaf(fn0, (float)a00, e0);
        float d01 = fmaf(fn0, (float)a01, e1);
        float d10 = fmaf(fn1, (float)a10, e0);
        float d11 = fmaf(fn1, (float)a11, e1);
        pmin0 = fminf(pmin0, fminf(d00, d01));
        pmin1 = fminf(pmin1, fminf(d10, d11));
        const float th0 = pmin0 + eps0, th1 = pmin1 + eps1;
        if (d00 <= th0) { if (cnt0 < CAP) { cnd0[cnt0] = k;     cdv0[cnt0] = d00; } cnt0++; }
        if (d01 <= th0) { if (cnt0 < CAP) { cnd0[cnt0] = k + 1; cdv0[cnt0] = d01; } cnt0++; }
        if (d10 <= th1) { if (cnt1 < CAP) { cnd1[cnt1] = k;     cdv1[cnt1] = d10; } cnt1++; }
        if (d11 <= th1) { if (cnt1 < CAP) { cnd1[cnt1] = k + 1; cdv1[cnt1] = d11; } cnt1++; }
    }

    // ---- Exact verify (validated fp32 sequential-d chain) + outputs per row ----
    float lsum = 0.f;
    #pragma unroll 1
    for (int r = 0; r < 2; r++) {
        const int row = row0 + r * CTA;
        const float4* xin = (const float4*)(feat + (gNB + row) * ND);
        float4 xv[16];
        #pragma unroll
        for (int i = 0; i < 16; i++) xv[i] = xin[i];
        const float xsq  = r ? xsq1 : xsq0;
        const float pmin = r ? pmin1 : pmin0;
        const float eps  = r ? eps1 : eps0;
        const int cnt    = r ? cnt1 : cnt0;
        const int* cnd   = r ? cnd1 : cnd0;
        const float* cdv = r ? cdv1 : cdv0;

        float best = FLT_MAX;
        int bk = 0;
        #define EXACT_K(kk)                                                    \
        {                                                                      \
            const float4* cp = (const float4*)(cbg + (size_t)(kk) * ND);       \
            float cr = 0.f;                                                    \
            _Pragma("unroll")                                                  \
            for (int i = 0; i < 16; i++) {                                     \
                float4 v = cp[i];                                              \
                cr = fmaf(xv[i].x, v.x, cr);                                   \
                cr = fmaf(xv[i].y, v.y, cr);                                   \
                cr = fmaf(xv[i].z, v.z, cr);                                   \
                cr = fmaf(xv[i].w, v.w, cr);                                   \
            }                                                                  \
            float dk = (xsq + sh_esq[kk]) - 2.0f * cr;                         \
            if (dk < best || (dk == best && (kk) < bk)) { best = dk; bk = (kk); } \
        }
        if (cnt > CAP) {
            for (int k = 0; k < NK; k++) EXACT_K(k);
        } else {
            const float th = pmin + eps;
            for (int i = 0; i < cnt; i++) {
                if (cdv[i] <= th) { int k = cnd[i]; EXACT_K(k); }
            }
        }
        #undef EXACT_K

        const float4* qp = (const float4*)(cbg + (size_t)bk * ND);
        float4* oq = (float4*)(out_q + (gNB + row) * ND);
        #pragma unroll
        for (int i = 0; i < 16; i++) {
            float4 qv = qp[i], fv = xv[i];
            float dx0 = qv.x - fv.x, dx1 = qv.y - fv.y;
            float dx2 = qv.z - fv.z, dx3 = qv.w - fv.w;
            lsum = fmaf(dx0, dx0, lsum);
            lsum = fmaf(dx1, dx1, lsum);
            lsum = fmaf(dx2, dx2, lsum);
            lsum = fmaf(dx3, dx3, lsum);
            if (write_q)
                oq[i] = make_float4(fv.x + dx0, fv.y + dx1, fv.z + dx2, fv.w + dx3);
        }
        if (write_idx) out_idx[gNB + row] = (float)bk;
    }

    // ---- Loss: warp shuffle -> shared -> double atomic; last CTA finalizes ----
    #pragma unroll
    for (int off = 16; off > 0; off >>= 1)
        lsum += __shfl_xor_sync(0xFFFFFFFFu, lsum, off);
    if ((tid & 31) == 0) sh_red[tid >> 5] = lsum;
    __syncthreads();
    if (tid == 0) {
        double s = 0.0;
        #pragma unroll
        for (int w = 0; w < CTA / 32; w++) s += (double)sh_red[w];
        atomicAdd(&g_loss_sum[g], s);
        __threadfence();
        unsigned int t = atomicAdd(&g_done, 1u);
        if (t == NCTAS - 1) {
            __threadfence();
            if (write_loss) {
                const double inv = 1.25 / ((double)NB * (double)ND);
                float tot = 0.f;
                for (int g2 = 0; g2 < NG; g2++) {
                    float pl = (float)(g_loss_sum[g2] * inv);
                    out_loss[g2] = pl;
                    tot += pl;
                }
                out_loss[NG] = tot;
            }
            for (int g2 = 0; g2 < NG; g2++) g_loss_sum[g2] = 0.0;
            g_done = 0;
        }
    }
}

extern "C" void kernel_launch(void* const* d_in, const int* in_sizes, int n_in,
                              void* d_out, int out_size) {
    const float* feat = (const float*)d_in[0];
    const float* cb   = (const float*)d_in[1];
    if (n_in >= 2 && in_sizes[0] == NG * NK * ND) {
        const float* t = feat; feat = cb; cb = t;
    }
    float* out = (float*)d_out;

    const long long q_elems   = (long long)NG * NB * ND;
    const long long idx_elems = (long long)NG * NB;
    const long long full_sz   = q_elems + NG + 1 + idx_elems;
    const int write_q    = ((long long)out_size >= q_elems);
    const int write_loss = ((long long)out_size >= q_elems + NG + 1);
    const int write_idx  = ((long long)out_size >= full_sz);

    dim3 grid(XBLK, NG);
    float* out_loss = out + q_elems;
    float* out_idx  = out + q_elems + NG + 1;
    vq_dp4a_kernel<<<grid, CTA>>>(feat, cb, out, out_loss, out_idx,
                                  write_q, write_loss, write_idx);
}